// round 11
// baseline (speedup 1.0000x reference)
#include <cuda_runtime.h>
#include <cuda_bf16.h>
#include <math.h>

// ---------------------------------------------------------------------------
// Attention_69226282877525: BERT-style MHA on sm_103a, tf32 mma.sync path.
//   B=2, F=T=2048, HIDDEN=1024, N_HEADS=16, HEAD_DIM=64
// R11 = R9 GEMM (reverted) + flash: Q in registers, K/V triple-buffered,
// ONE __syncthreads per T-tile (was 3) -> warps decoupled within a tile.
// ---------------------------------------------------------------------------

#define BATCH   2
#define SEQ     2048
#define HIDDEN  1024
#define NHEADS  16
#define HDIM    64
#define MROWS   (BATCH * SEQ)      // 4096

// Scratch for Q/K/V in [B][N][S][H] layout, tf32-pre-rounded fp32 (16 MB each)
__device__ float g_Qs[(size_t)BATCH * NHEADS * SEQ * HDIM];
__device__ float g_Ks[(size_t)BATCH * NHEADS * SEQ * HDIM];
__device__ float g_Vs[(size_t)BATCH * NHEADS * SEQ * HDIM];
// Packed attention mask bits: [B][F][T/32] (1 MB)
__device__ unsigned g_Mbits[(size_t)BATCH * SEQ * (SEQ / 32)];

// --------------------------- helpers ---------------------------------------
__device__ __forceinline__ unsigned f2tf(float x) {
    unsigned r;
    asm("cvt.rna.tf32.f32 %0, %1;" : "=r"(r) : "f"(x));
    return r;
}
__device__ __forceinline__ float f2tf_f(float x) {
    return __uint_as_float(f2tf(x));
}
__device__ __forceinline__ void cvt4(float4& v) {
    v.x = f2tf_f(v.x); v.y = f2tf_f(v.y); v.z = f2tf_f(v.z); v.w = f2tf_f(v.w);
}
__device__ __forceinline__ void mma_tf32(float c[4], const unsigned a[4],
                                         const unsigned b[2]) {
    asm volatile(
        "mma.sync.aligned.m16n8k8.row.col.f32.tf32.tf32.f32 "
        "{%0,%1,%2,%3}, {%4,%5,%6,%7}, {%8,%9}, {%0,%1,%2,%3};\n"
        : "+f"(c[0]), "+f"(c[1]), "+f"(c[2]), "+f"(c[3])
        : "r"(a[0]), "r"(a[1]), "r"(a[2]), "r"(a[3]), "r"(b[0]), "r"(b[1]));
}
__device__ __forceinline__ void cp_async16(float* dst_smem, const float* src) {
    unsigned d = (unsigned)__cvta_generic_to_shared(dst_smem);
    asm volatile("cp.async.cg.shared.global [%0], [%1], 16;" :: "r"(d), "l"(src));
}
__device__ __forceinline__ void cp_commit() {
    asm volatile("cp.async.commit_group;");
}
template<int N> __device__ __forceinline__ void cp_wait() {
    asm volatile("cp.async.wait_group %0;" :: "n"(N));
}

// ---------------------------------------------------------------------------
// Pack mask [B,F,T] int32 -> bitmask [B,F,T/32]. One warp per (b,f) row.
// ---------------------------------------------------------------------------
__global__ __launch_bounds__(256) void mask_bits_kernel(
    const int* __restrict__ mask, unsigned* __restrict__ bits)
{
    const int gw   = (blockIdx.x * 256 + threadIdx.x) >> 5;   // row index
    const int lane = threadIdx.x & 31;
    if (gw >= BATCH * SEQ) return;
    const int* mp = mask + (size_t)gw * SEQ;
    unsigned* bp  = bits + (size_t)gw * (SEQ / 32);
    #pragma unroll 4
    for (int c = 0; c < SEQ / 32; c++) {
        const int v = mp[c * 32 + lane];
        const unsigned w = __ballot_sync(0xffffffffu, v != 0);
        if (lane == 0) bp[c] = w;
    }
}

// ---------------------------------------------------------------------------
// Merged QKV projection GEMM (tf32 mma): blockIdx.z in {Q,K,V}.
// CTA 256 thr, tile 128x128, ktile 16, 8 warps (4m x 2n), warp tile 32x64.
// (R9 version, register-staged double buffer.)
// ---------------------------------------------------------------------------
#define GA_STR 20
#define GB_STR 136
#define GEMM_SMEM ((2 * 128 * GA_STR + 2 * 16 * GB_STR) * 4)   // 37888 bytes

__global__ __launch_bounds__(256, 2) void gemm_mma_kernel(
    const float* __restrict__ Xq, const float* __restrict__ Xkv,
    const float* __restrict__ Wq, const float* __restrict__ bq,
    const float* __restrict__ Wk, const float* __restrict__ bk,
    const float* __restrict__ Wv, const float* __restrict__ bv,
    float* __restrict__ oq, float* __restrict__ ok, float* __restrict__ ov)
{
    extern __shared__ float smg[];
    float* As = smg;                       // [2][128][GA_STR]
    float* Bs = smg + 2 * 128 * GA_STR;    // [2][16][GB_STR]

    const float* X; const float* W; const float* bias; float* out;
    if (blockIdx.z == 0)      { X = Xq;  W = Wq; bias = bq; out = oq; }
    else if (blockIdx.z == 1) { X = Xkv; W = Wk; bias = bk; out = ok; }
    else                      { X = Xkv; W = Wv; bias = bv; out = ov; }

    const int tid  = threadIdx.x;
    const int w    = tid >> 5;
    const int lane = tid & 31;
    const int gid  = lane >> 2;
    const int tid4 = lane & 3;
    const int wm   = w & 3;
    const int wn   = w >> 2;
    const int row0 = blockIdx.y * 128;
    const int col0 = blockIdx.x * 128;

    float4 ar[2], br[2];

    #pragma unroll
    for (int i = 0; i < 2; i++) {
        const int idx = tid + i * 256;
        { const int r = idx >> 2, c4 = idx & 3;
          ar[i] = *(const float4*)(X + (size_t)(row0 + r) * HIDDEN + c4 * 4); }
        { const int r = idx >> 5, c4 = idx & 31;
          br[i] = *(const float4*)(W + (size_t)r * HIDDEN + col0 + c4 * 4); }
    }
    #pragma unroll
    for (int i = 0; i < 2; i++) {
        const int idx = tid + i * 256;
        cvt4(ar[i]); cvt4(br[i]);
        { const int r = idx >> 2, c4 = idx & 3;
          *(float4*)(As + r * GA_STR + c4 * 4) = ar[i]; }
        { const int r = idx >> 5, c4 = idx & 31;
          *(float4*)(Bs + r * GB_STR + c4 * 4) = br[i]; }
    }
    __syncthreads();

    float C[2][8][4] = {};

    for (int kt = 0; kt < 64; kt++) {
        const int buf = kt & 1;
        if (kt < 63) {
            const int k0 = (kt + 1) * 16;
            #pragma unroll
            for (int i = 0; i < 2; i++) {
                const int idx = tid + i * 256;
                { const int r = idx >> 2, c4 = idx & 3;
                  ar[i] = *(const float4*)(X + (size_t)(row0 + r) * HIDDEN + k0 + c4 * 4); }
                { const int r = idx >> 5, c4 = idx & 31;
                  br[i] = *(const float4*)(W + (size_t)(k0 + r) * HIDDEN + col0 + c4 * 4); }
            }
        }
        const float* Ab = As + buf * 128 * GA_STR;
        const float* Bb = Bs + buf * 16 * GB_STR;
        #pragma unroll
        for (int ks = 0; ks < 2; ks++) {
            unsigned a[2][4];
            #pragma unroll
            for (int mb = 0; mb < 2; mb++) {
                const int base = (wm * 32 + mb * 16 + gid) * GA_STR + ks * 8 + tid4;
                a[mb][0] = __float_as_uint(Ab[base]);
                a[mb][1] = __float_as_uint(Ab[base + 8 * GA_STR]);
                a[mb][2] = __float_as_uint(Ab[base + 4]);
                a[mb][3] = __float_as_uint(Ab[base + 8 * GA_STR + 4]);
            }
            #pragma unroll
            for (int nb = 0; nb < 8; nb++) {
                unsigned bf[2];
                const int bbase = (ks * 8 + tid4) * GB_STR + wn * 64 + nb * 8 + gid;
                bf[0] = __float_as_uint(Bb[bbase]);
                bf[1] = __float_as_uint(Bb[bbase + 4 * GB_STR]);
                mma_tf32(C[0][nb], a[0], bf);
                mma_tf32(C[1][nb], a[1], bf);
            }
        }
        if (kt < 63) {
            float* An = As + ((kt + 1) & 1) * 128 * GA_STR;
            float* Bn = Bs + ((kt + 1) & 1) * 16 * GB_STR;
            #pragma unroll
            for (int i = 0; i < 2; i++) {
                const int idx = tid + i * 256;
                cvt4(ar[i]); cvt4(br[i]);
                { const int r = idx >> 2, c4 = idx & 3;
                  *(float4*)(An + r * GA_STR + c4 * 4) = ar[i]; }
                { const int r = idx >> 5, c4 = idx & 31;
                  *(float4*)(Bn + r * GB_STR + c4 * 4) = br[i]; }
            }
        }
        __syncthreads();
    }

    // epilogue: bias + tf32 round + transpose-store to [B][N][S][H]
    const int colbase = col0 + wn * 64;
    const int nhead   = colbase >> 6;
    #pragma unroll
    for (int mb = 0; mb < 2; mb++) {
        #pragma unroll
        for (int h = 0; h < 2; h++) {
            const int row = row0 + wm * 32 + mb * 16 + gid + 8 * h;
            const int b   = row >> 11;
            const int s   = row & 2047;
            float* op = out + (((size_t)b * NHEADS + nhead) * SEQ + s) * HDIM;
            #pragma unroll
            for (int nb = 0; nb < 8; nb++) {
                const int hh = nb * 8 + 2 * tid4;
                float2 v;
                v.x = f2tf_f(C[mb][nb][2 * h]     + bias[colbase + hh]);
                v.y = f2tf_f(C[mb][nb][2 * h + 1] + bias[colbase + hh + 1]);
                *(float2*)(op + hh) = v;
            }
        }
    }
}

// ---------------------------------------------------------------------------
// Flash attention (tf32 mma): CTA 128 thr = 4 warps x 16 f-rows, f-tile 64,
// T-tile 64. Q held in REGISTERS (loaded once). K/V triple-buffered in SMEM
// (105KB -> 2 CTAs/SM); exactly ONE __syncthreads per tile.
// No-max softmax; bitmask.
// ---------------------------------------------------------------------------
#define FK_STR 68
#define FV_STR 72
#define KBUF (64 * FK_STR)
#define VBUF (64 * FV_STR)
#define ATT_SMEM ((3 * KBUF + 3 * VBUF) * 4)   // 107520

__global__ __launch_bounds__(128, 2) void flash_mma_kernel(
    const float* __restrict__ Q, const float* __restrict__ K,
    const float* __restrict__ V, const unsigned* __restrict__ mbitsg,
    float* __restrict__ out)
{
    extern __shared__ float sm[];
    float* Ks3 = sm;                       // [3][64][68]
    float* Vs3 = sm + 3 * KBUF;            // [3][64][72]

    const int tid  = threadIdx.x;          // 128
    const int w    = tid >> 5;             // 0..3 -> f-rows w*16..w*16+15
    const int lane = tid & 31;
    const int gid  = lane >> 2;
    const int tid4 = lane & 3;

    const int bn = blockIdx.y;             // b*16 + head
    const int b  = bn >> 4;
    const int nh = bn & 15;
    const int f0 = blockIdx.x * 64;

    const float* Kp = K + (size_t)bn * SEQ * HDIM;
    const float* Vp = V + (size_t)bn * SEQ * HDIM;
    const unsigned* Mb = mbitsg + (size_t)b * SEQ * (SEQ / 32);

    // prologue: K0/V0 (group 0), K1/V1 (group 1)
    #pragma unroll
    for (int i = 0; i < 8; i++) {
        const int idx = tid + i * 128;
        const int r = idx >> 4, c = idx & 15;
        cp_async16(Ks3 + r * FK_STR + c * 4, Kp + (size_t)r * HDIM + c * 4);
        cp_async16(Vs3 + r * FV_STR + c * 4, Vp + (size_t)r * HDIM + c * 4);
    }
    cp_commit();
    #pragma unroll
    for (int i = 0; i < 8; i++) {
        const int idx = tid + i * 128;
        const int r = idx >> 4, c = idx & 15;
        cp_async16(Ks3 + KBUF + r * FK_STR + c * 4,
                   Kp + (size_t)(64 + r) * HDIM + c * 4);
        cp_async16(Vs3 + VBUF + r * FV_STR + c * 4,
                   Vp + (size_t)(64 + r) * HDIM + c * 4);
    }
    cp_commit();

    // Q fragments in registers (loaded once from global; values tf32-rounded)
    unsigned qf[8][4];
    {
        const float* Qw = Q + ((size_t)bn * SEQ + f0 + w * 16) * HDIM;
        #pragma unroll
        for (int ks = 0; ks < 8; ks++) {
            qf[ks][0] = __float_as_uint(Qw[(size_t)gid * HDIM + ks * 8 + tid4]);
            qf[ks][1] = __float_as_uint(Qw[(size_t)(gid + 8) * HDIM + ks * 8 + tid4]);
            qf[ks][2] = __float_as_uint(Qw[(size_t)gid * HDIM + ks * 8 + tid4 + 4]);
            qf[ks][3] = __float_as_uint(Qw[(size_t)(gid + 8) * HDIM + ks * 8 + tid4 + 4]);
        }
    }

    float O[8][4] = {};
    float lrow[2] = {};

    for (int u = 0; u < 32; u++) {
        // groups outstanding before wait: {u, u+1} (u<31) or {31} (u==31)
        if (u < 31) cp_wait<1>(); else cp_wait<0>();
        __syncthreads();     // tile u resident; all warps done reading tile u-1

        // prefetch tile u+2 into buffer (u+2)%3 (last read finished at tile u-1)
        if (u + 2 < 32) {
            const int s = (u + 2) % 3;
            const size_t t2 = (size_t)(u + 2) * 64;
            #pragma unroll
            for (int i = 0; i < 8; i++) {
                const int idx = tid + i * 128;
                const int r = idx >> 4, c = idx & 15;
                cp_async16(Ks3 + s * KBUF + r * FK_STR + c * 4,
                           Kp + (t2 + r) * HDIM + c * 4);
                cp_async16(Vs3 + s * VBUF + r * FV_STR + c * 4,
                           Vp + (t2 + r) * HDIM + c * 4);
            }
            cp_commit();
        }

        const float* Ksb = Ks3 + (u % 3) * KBUF;
        const float* Vsb = Vs3 + (u % 3) * VBUF;

        // mask bits for this tile (issued early, consumed after QK)
        unsigned long long mbits[2];
        #pragma unroll
        for (int h = 0; h < 2; h++) {
            const int rg = f0 + w * 16 + gid + 8 * h;
            const uint2 mm = *(const uint2*)(Mb + (size_t)rg * (SEQ / 32) + u * 2);
            mbits[h] = (unsigned long long)mm.x |
                       ((unsigned long long)mm.y << 32);
        }

        // ---- S = Q @ K^T (A from registers) ----
        float S[8][4] = {};
        #pragma unroll
        for (int ks = 0; ks < 8; ks++) {
            #pragma unroll
            for (int nb = 0; nb < 8; nb++) {
                unsigned bf[2];
                const int bbase = (nb * 8 + gid) * FK_STR + ks * 8 + tid4;
                bf[0] = __float_as_uint(Ksb[bbase]);
                bf[1] = __float_as_uint(Ksb[bbase + 4]);
                mma_tf32(S[nb], qf[ks], bf);
            }
        }

        // ---- no-max softmax: p = bit ? exp(0.125*s) : 0 ----
        #pragma unroll
        for (int h = 0; h < 2; h++) {
            const unsigned long long m64 = mbits[h];
            float ls = 0.0f;
            #pragma unroll
            for (int nb = 0; nb < 8; nb++) {
                const int pos = nb * 8 + 2 * tid4;
                const float p0 = ((m64 >> pos) & 1ULL)
                               ? __expf(0.125f * S[nb][2 * h]) : 0.0f;
                const float p1 = ((m64 >> (pos + 1)) & 1ULL)
                               ? __expf(0.125f * S[nb][2 * h + 1]) : 0.0f;
                ls += p0 + p1;
                S[nb][2 * h]     = p0;
                S[nb][2 * h + 1] = p1;
            }
            lrow[h] += ls;
        }

        // ---- O += P @ V : shuffle-transpose P C-frag -> A-frag ----
        const int src0 = (lane & 28) | (tid4 >> 1);
        const int src1 = src0 + 2;
        const bool odd = (tid4 & 1);
        #pragma unroll
        for (int kt = 0; kt < 8; kt++) {
            unsigned a[4];
            {
                float e0 = __shfl_sync(0xffffffffu, S[kt][0], src0);
                float o0 = __shfl_sync(0xffffffffu, S[kt][1], src0);
                float e1 = __shfl_sync(0xffffffffu, S[kt][0], src1);
                float o1 = __shfl_sync(0xffffffffu, S[kt][1], src1);
                float e2 = __shfl_sync(0xffffffffu, S[kt][2], src0);
                float o2 = __shfl_sync(0xffffffffu, S[kt][3], src0);
                float e3 = __shfl_sync(0xffffffffu, S[kt][2], src1);
                float o3 = __shfl_sync(0xffffffffu, S[kt][3], src1);
                a[0] = f2tf(odd ? o0 : e0);
                a[1] = f2tf(odd ? o2 : e2);
                a[2] = f2tf(odd ? o1 : e1);
                a[3] = f2tf(odd ? o3 : e3);
            }
            #pragma unroll
            for (int nb = 0; nb < 8; nb++) {
                unsigned bf[2];
                const int vbase = (kt * 8 + tid4) * FV_STR + nb * 8 + gid;
                bf[0] = __float_as_uint(Vsb[vbase]);
                bf[1] = __float_as_uint(Vsb[vbase + 4 * FV_STR]);
                mma_tf32(O[nb], a, bf);
            }
        }
        // no end-of-tile sync: buffer (u%3) is next overwritten by the
        // prefetch issued in tile u+1, which runs after tile u+1's top sync.
    }

    // ---- epilogue: reduce row sums once, normalize, store ----
    #pragma unroll
    for (int h = 0; h < 2; h++) {
        float l = lrow[h];
        l += __shfl_xor_sync(0xffffffffu, l, 1);
        l += __shfl_xor_sync(0xffffffffu, l, 2);
        const float linv = 1.0f / l;
        const int rg = f0 + w * 16 + gid + 8 * h;
        float* op = out + ((size_t)b * SEQ + rg) * HIDDEN + nh * HDIM;
        #pragma unroll
        for (int nb = 0; nb < 8; nb++) {
            float2 v;
            v.x = O[nb][2 * h] * linv;
            v.y = O[nb][2 * h + 1] * linv;
            *(float2*)(op + nb * 8 + 2 * tid4) = v;
        }
    }
}

// ---------------------------------------------------------------------------
// kernel_launch
// ---------------------------------------------------------------------------
extern "C" void kernel_launch(void* const* d_in, const int* in_sizes, int n_in,
                              void* d_out, int out_size)
{
    (void)in_sizes; (void)n_in; (void)out_size;

    const float* from_t = (const float*)d_in[0];
    const float* to_t   = (const float*)d_in[1];
    const int*   msk    = (const int*)d_in[2];
    const float* Wq     = (const float*)d_in[3];
    const float* bq     = (const float*)d_in[4];
    const float* Wk     = (const float*)d_in[5];
    const float* bk     = (const float*)d_in[6];
    const float* Wv     = (const float*)d_in[7];
    const float* bv     = (const float*)d_in[8];
    float* out = (float*)d_out;

    float *qp, *kp, *vp; unsigned* mb;
    cudaGetSymbolAddress((void**)&qp, g_Qs);
    cudaGetSymbolAddress((void**)&kp, g_Ks);
    cudaGetSymbolAddress((void**)&vp, g_Vs);
    cudaGetSymbolAddress((void**)&mb, g_Mbits);

    cudaFuncSetAttribute(gemm_mma_kernel,
                         cudaFuncAttributeMaxDynamicSharedMemorySize, GEMM_SMEM);
    cudaFuncSetAttribute(flash_mma_kernel,
                         cudaFuncAttributeMaxDynamicSharedMemorySize, ATT_SMEM);

    // pack mask to bits (independent of GEMM outputs)
    mask_bits_kernel<<<(MROWS * 32 + 255) / 256, 256>>>(msk, mb);

    dim3 gg(HIDDEN / 128, MROWS / 128, 3);   // (8, 32, 3)
    gemm_mma_kernel<<<gg, 256, GEMM_SMEM>>>(from_t, to_t, Wq, bq, Wk, bk,
                                            Wv, bv, qp, kp, vp);

    dim3 gf(SEQ / 64, BATCH * NHEADS);       // (32, 32) = 1024 CTAs
    flash_mma_kernel<<<gf, 128, ATT_SMEM>>>(qp, kp, vp, mb, out);
}

// round 12
// speedup vs baseline: 1.5148x; 1.5148x over previous
#include <cuda_runtime.h>
#include <cuda_fp16.h>
#include <math.h>

// ---------------------------------------------------------------------------
// Attention_69226282877525: BERT-style MHA on sm_103a.
//   B=2, F=T=2048, HIDDEN=1024, N_HEADS=16, HEAD_DIM=64
// R12 = R9 GEMM (tf32 mainloop) with fp16 outputs (V transposed [H][S] via
// smem) + flash rebuilt on fp16 m16n8k16: half the mma count, half the LDS
// bytes, and the QK C-frag == PV A-frag (no shuffle transpose).
// ---------------------------------------------------------------------------

#define BATCH   2
#define SEQ     2048
#define HIDDEN  1024
#define NHEADS  16
#define HDIM    64
#define MROWS   (BATCH * SEQ)      // 4096

// Scratch (half): Q/K in [B][N][S][H]; V TRANSPOSED in [B][N][H][S].
__device__ __half g_Qh[(size_t)BATCH * NHEADS * SEQ * HDIM];
__device__ __half g_Kh[(size_t)BATCH * NHEADS * SEQ * HDIM];
__device__ __half g_Vth[(size_t)BATCH * NHEADS * SEQ * HDIM];
// Packed attention mask bits: [B][F][T/32]
__device__ unsigned g_Mbits[(size_t)BATCH * SEQ * (SEQ / 32)];

// --------------------------- helpers ---------------------------------------
__device__ __forceinline__ unsigned f2tf(float x) {
    unsigned r;
    asm("cvt.rna.tf32.f32 %0, %1;" : "=r"(r) : "f"(x));
    return r;
}
__device__ __forceinline__ float f2tf_f(float x) {
    return __uint_as_float(f2tf(x));
}
__device__ __forceinline__ void cvt4(float4& v) {
    v.x = f2tf_f(v.x); v.y = f2tf_f(v.y); v.z = f2tf_f(v.z); v.w = f2tf_f(v.w);
}
__device__ __forceinline__ void mma_tf32(float c[4], const unsigned a[4],
                                         const unsigned b[2]) {
    asm volatile(
        "mma.sync.aligned.m16n8k8.row.col.f32.tf32.tf32.f32 "
        "{%0,%1,%2,%3}, {%4,%5,%6,%7}, {%8,%9}, {%0,%1,%2,%3};\n"
        : "+f"(c[0]), "+f"(c[1]), "+f"(c[2]), "+f"(c[3])
        : "r"(a[0]), "r"(a[1]), "r"(a[2]), "r"(a[3]), "r"(b[0]), "r"(b[1]));
}
__device__ __forceinline__ void mma_f16(float c[4], const unsigned a[4],
                                        const unsigned b[2]) {
    asm volatile(
        "mma.sync.aligned.m16n8k16.row.col.f32.f16.f16.f32 "
        "{%0,%1,%2,%3}, {%4,%5,%6,%7}, {%8,%9}, {%0,%1,%2,%3};\n"
        : "+f"(c[0]), "+f"(c[1]), "+f"(c[2]), "+f"(c[3])
        : "r"(a[0]), "r"(a[1]), "r"(a[2]), "r"(a[3]), "r"(b[0]), "r"(b[1]));
}
__device__ __forceinline__ unsigned packh2(float x, float y) {
    __half2 h = __floats2half2_rn(x, y);
    return *(unsigned*)&h;
}
__device__ __forceinline__ void cp_async16(void* dst_smem, const void* src) {
    unsigned d = (unsigned)__cvta_generic_to_shared(dst_smem);
    asm volatile("cp.async.cg.shared.global [%0], [%1], 16;" :: "r"(d), "l"(src));
}
__device__ __forceinline__ void cp_commit() {
    asm volatile("cp.async.commit_group;");
}
template<int N> __device__ __forceinline__ void cp_wait() {
    asm volatile("cp.async.wait_group %0;" :: "n"(N));
}

// ---------------------------------------------------------------------------
// Pack mask [B,F,T] int32 -> bitmask [B,F,T/32]. One warp per (b,f) row.
// ---------------------------------------------------------------------------
__global__ __launch_bounds__(256) void mask_bits_kernel(
    const int* __restrict__ mask, unsigned* __restrict__ bits)
{
    const int gw   = (blockIdx.x * 256 + threadIdx.x) >> 5;
    const int lane = threadIdx.x & 31;
    if (gw >= BATCH * SEQ) return;
    const int* mp = mask + (size_t)gw * SEQ;
    unsigned* bp  = bits + (size_t)gw * (SEQ / 32);
    #pragma unroll 4
    for (int c = 0; c < SEQ / 32; c++) {
        const int v = mp[c * 32 + lane];
        const unsigned w = __ballot_sync(0xffffffffu, v != 0);
        if (lane == 0) bp[c] = w;
    }
}

// ---------------------------------------------------------------------------
// Merged QKV projection GEMM (tf32 mma mainloop, half outputs).
// blockIdx.z in {Q,K,V}. Q/K: [B][N][S][H] half. V: [B][N][H][S] half via
// smem transpose in the epilogue.
// ---------------------------------------------------------------------------
#define GA_STR 20
#define GB_STR 136
#define GEMM_SMEM ((2 * 128 * GA_STR + 2 * 16 * GB_STR) * 4)   // 37888 bytes
#define VT_STR 136   // halves; transpose buffer 128 x VT_STR half = 34816 B

__global__ __launch_bounds__(256, 2) void gemm_mma_kernel(
    const float* __restrict__ Xq, const float* __restrict__ Xkv,
    const float* __restrict__ Wq, const float* __restrict__ bq,
    const float* __restrict__ Wk, const float* __restrict__ bk,
    const float* __restrict__ Wv, const float* __restrict__ bv,
    __half* __restrict__ oq, __half* __restrict__ ok, __half* __restrict__ ov)
{
    extern __shared__ float smg[];
    float* As = smg;                       // [2][128][GA_STR]
    float* Bs = smg + 2 * 128 * GA_STR;    // [2][16][GB_STR]

    const float* X; const float* W; const float* bias; __half* out;
    if (blockIdx.z == 0)      { X = Xq;  W = Wq; bias = bq; out = oq; }
    else if (blockIdx.z == 1) { X = Xkv; W = Wk; bias = bk; out = ok; }
    else                      { X = Xkv; W = Wv; bias = bv; out = ov; }
    const bool vtrans = (blockIdx.z == 2);

    const int tid  = threadIdx.x;
    const int w    = tid >> 5;
    const int lane = tid & 31;
    const int gid  = lane >> 2;
    const int tid4 = lane & 3;
    const int wm   = w & 3;
    const int wn   = w >> 2;
    const int row0 = blockIdx.y * 128;
    const int col0 = blockIdx.x * 128;

    float4 ar[2], br[2];

    #pragma unroll
    for (int i = 0; i < 2; i++) {
        const int idx = tid + i * 256;
        { const int r = idx >> 2, c4 = idx & 3;
          ar[i] = *(const float4*)(X + (size_t)(row0 + r) * HIDDEN + c4 * 4); }
        { const int r = idx >> 5, c4 = idx & 31;
          br[i] = *(const float4*)(W + (size_t)r * HIDDEN + col0 + c4 * 4); }
    }
    #pragma unroll
    for (int i = 0; i < 2; i++) {
        const int idx = tid + i * 256;
        cvt4(ar[i]); cvt4(br[i]);
        { const int r = idx >> 2, c4 = idx & 3;
          *(float4*)(As + r * GA_STR + c4 * 4) = ar[i]; }
        { const int r = idx >> 5, c4 = idx & 31;
          *(float4*)(Bs + r * GB_STR + c4 * 4) = br[i]; }
    }
    __syncthreads();

    float C[2][8][4] = {};

    for (int kt = 0; kt < 64; kt++) {
        const int buf = kt & 1;
        if (kt < 63) {
            const int k0 = (kt + 1) * 16;
            #pragma unroll
            for (int i = 0; i < 2; i++) {
                const int idx = tid + i * 256;
                { const int r = idx >> 2, c4 = idx & 3;
                  ar[i] = *(const float4*)(X + (size_t)(row0 + r) * HIDDEN + k0 + c4 * 4); }
                { const int r = idx >> 5, c4 = idx & 31;
                  br[i] = *(const float4*)(W + (size_t)(k0 + r) * HIDDEN + col0 + c4 * 4); }
            }
        }
        const float* Ab = As + buf * 128 * GA_STR;
        const float* Bb = Bs + buf * 16 * GB_STR;
        #pragma unroll
        for (int ks = 0; ks < 2; ks++) {
            unsigned a[2][4];
            #pragma unroll
            for (int mb = 0; mb < 2; mb++) {
                const int base = (wm * 32 + mb * 16 + gid) * GA_STR + ks * 8 + tid4;
                a[mb][0] = __float_as_uint(Ab[base]);
                a[mb][1] = __float_as_uint(Ab[base + 8 * GA_STR]);
                a[mb][2] = __float_as_uint(Ab[base + 4]);
                a[mb][3] = __float_as_uint(Ab[base + 8 * GA_STR + 4]);
            }
            #pragma unroll
            for (int nb = 0; nb < 8; nb++) {
                unsigned bf[2];
                const int bbase = (ks * 8 + tid4) * GB_STR + wn * 64 + nb * 8 + gid;
                bf[0] = __float_as_uint(Bb[bbase]);
                bf[1] = __float_as_uint(Bb[bbase + 4 * GB_STR]);
                mma_tf32(C[0][nb], a[0], bf);
                mma_tf32(C[1][nb], a[1], bf);
            }
        }
        if (kt < 63) {
            float* An = As + ((kt + 1) & 1) * 128 * GA_STR;
            float* Bn = Bs + ((kt + 1) & 1) * 16 * GB_STR;
            #pragma unroll
            for (int i = 0; i < 2; i++) {
                const int idx = tid + i * 256;
                cvt4(ar[i]); cvt4(br[i]);
                { const int r = idx >> 2, c4 = idx & 3;
                  *(float4*)(An + r * GA_STR + c4 * 4) = ar[i]; }
                { const int r = idx >> 5, c4 = idx & 31;
                  *(float4*)(Bn + r * GB_STR + c4 * 4) = br[i]; }
            }
        }
        __syncthreads();
    }

    const int colbase = col0 + wn * 64;
    const int nhead   = colbase >> 6;

    if (!vtrans) {
        // Q/K: half2 store to [B][N][S][H]
        #pragma unroll
        for (int mb = 0; mb < 2; mb++) {
            #pragma unroll
            for (int h = 0; h < 2; h++) {
                const int row = row0 + wm * 32 + mb * 16 + gid + 8 * h;
                const int b   = row >> 11;
                const int s   = row & 2047;
                __half* op = out + (((size_t)b * NHEADS + nhead) * SEQ + s) * HDIM;
                #pragma unroll
                for (int nb = 0; nb < 8; nb++) {
                    const int hh = nb * 8 + 2 * tid4;
                    const unsigned v = packh2(C[mb][nb][2 * h]     + bias[colbase + hh],
                                              C[mb][nb][2 * h + 1] + bias[colbase + hh + 1]);
                    *(unsigned*)(op + hh) = v;
                }
            }
        }
    } else {
        // V: transpose through smem, store [B][N][H][S] half, coalesced.
        __half* T = (__half*)smg;          // [128 h][VT_STR]
        #pragma unroll
        for (int mb = 0; mb < 2; mb++) {
            #pragma unroll
            for (int h = 0; h < 2; h++) {
                const int srow = wm * 32 + mb * 16 + gid + 8 * h;   // 0..127
                #pragma unroll
                for (int nb = 0; nb < 8; nb++) {
                    const int hh = wn * 64 + nb * 8 + 2 * tid4;     // tile col
                    T[(size_t)hh * VT_STR + srow] =
                        __float2half_rn(C[mb][nb][2 * h] + bias[col0 + hh]);
                    T[(size_t)(hh + 1) * VT_STR + srow] =
                        __float2half_rn(C[mb][nb][2 * h + 1] + bias[col0 + hh + 1]);
                }
            }
        }
        __syncthreads();
        // cooperative coalesced store: 2 threads per h-row, 64 halves each
        const int r   = tid >> 1;              // 0..127 (tile col = h)
        const int seg = (tid & 1) * 64;        // s segment
        const int hg  = col0 + r;
        const int n   = hg >> 6;
        const int hl  = hg & 63;
        const int b   = row0 >> 11;
        const int sb  = (row0 & 2047) + seg;
        __half* op = ov + (((size_t)b * NHEADS + n) * HDIM + hl) * SEQ + sb;
        const uint4* Tr = (const uint4*)(T + (size_t)r * VT_STR + seg);
        #pragma unroll
        for (int j = 0; j < 8; j++)
            ((uint4*)op)[j] = Tr[j];
    }
}

// ---------------------------------------------------------------------------
// Flash attention (fp16 m16n8k16): CTA 128 thr = 4 warps x 16 f-rows,
// f-tile 64, T-tile 64. Q fragments in registers (loaded once). K [t][h] and
// V^T [h][t] half tiles in SMEM (18.4KB), single-buffered with split waits.
// QK C-frag feeds PV A-frag directly (no shuffles). No-max softmax; bitmask.
// ---------------------------------------------------------------------------
#define FKS 72      // K tile row stride (halves)
#define FVS 72      // VT tile row stride (halves)
#define ATT_SMEM ((64 * FKS + 64 * FVS) * 2)   // 18432 bytes

__global__ __launch_bounds__(128, 4) void flash_mma_kernel(
    const __half* __restrict__ Q, const __half* __restrict__ K,
    const __half* __restrict__ Vt, const unsigned* __restrict__ mbitsg,
    float* __restrict__ out)
{
    extern __shared__ __half smh[];
    __half* Ks = smh;                      // [64 t][FKS]
    __half* Vs = smh + 64 * FKS;           // [64 h][FVS]

    const int tid  = threadIdx.x;          // 128
    const int w    = tid >> 5;             // 0..3 -> f-rows w*16..w*16+15
    const int lane = tid & 31;
    const int gid  = lane >> 2;
    const int tid4 = lane & 3;

    const int bn = blockIdx.y;             // b*16 + head
    const int b  = bn >> 4;
    const int nh = bn & 15;
    const int f0 = blockIdx.x * 64;

    const __half* Kp = K + (size_t)bn * SEQ * HDIM;    // [t][h]
    const __half* Vp = Vt + (size_t)bn * HDIM * SEQ;   // [h][t]
    const unsigned* Mb = mbitsg + (size_t)b * SEQ * (SEQ / 32);

    // prologue: K0 (group 0), V0 (group 1). Tile = 64 rows x 128B.
    #pragma unroll
    for (int i = 0; i < 4; i++) {
        const int idx = tid + i * 128;
        const int r = idx >> 3, c = idx & 7;
        cp_async16(Ks + r * FKS + c * 8, Kp + (size_t)r * HDIM + c * 8);
    }
    cp_commit();
    #pragma unroll
    for (int i = 0; i < 4; i++) {
        const int idx = tid + i * 128;
        const int r = idx >> 3, c = idx & 7;
        cp_async16(Vs + r * FVS + c * 8, Vp + (size_t)r * SEQ + c * 8);
    }
    cp_commit();

    // Q fragments in registers: a-frags for m16n8k16 (half2 words)
    unsigned qf[4][4];
    {
        const __half* Qw = Q + ((size_t)bn * SEQ + f0 + w * 16) * HDIM;
        #pragma unroll
        for (int ks = 0; ks < 4; ks++) {
            const int c = ks * 16 + 2 * tid4;
            qf[ks][0] = *(const unsigned*)(Qw + (size_t)gid * HDIM + c);
            qf[ks][1] = *(const unsigned*)(Qw + (size_t)(gid + 8) * HDIM + c);
            qf[ks][2] = *(const unsigned*)(Qw + (size_t)gid * HDIM + c + 8);
            qf[ks][3] = *(const unsigned*)(Qw + (size_t)(gid + 8) * HDIM + c + 8);
        }
    }

    float O[8][4] = {};
    float lrow[2] = {};

    for (int t0 = 0; t0 < SEQ; t0 += 64) {
        cp_wait<1>();          // K(t) ready (V(t) may still be in flight)
        __syncthreads();

        // mask bits for this tile (hidden behind QK mma)
        unsigned long long mbits[2];
        #pragma unroll
        for (int h = 0; h < 2; h++) {
            const int rg = f0 + w * 16 + gid + 8 * h;
            const uint2 mm = *(const uint2*)(Mb + (size_t)rg * (SEQ / 32) + (t0 >> 5));
            mbits[h] = (unsigned long long)mm.x |
                       ((unsigned long long)mm.y << 32);
        }

        // ---- S = Q @ K^T (fp16, warp tile 16x64) ----
        float S[8][4] = {};
        #pragma unroll
        for (int ks = 0; ks < 4; ks++) {
            #pragma unroll
            for (int nb = 0; nb < 8; nb++) {
                unsigned bf[2];
                const int bb = (nb * 8 + gid) * FKS + ks * 16 + 2 * tid4;
                bf[0] = *(const unsigned*)(Ks + bb);
                bf[1] = *(const unsigned*)(Ks + bb + 8);
                mma_f16(S[nb], qf[ks], bf);
            }
        }
        __syncthreads();       // all warps done reading K tile

        // prefetch next K tile (overlaps softmax + PV)
        if (t0 + 64 < SEQ) {
            const __half* kn = Kp + (size_t)(t0 + 64) * HDIM;
            #pragma unroll
            for (int i = 0; i < 4; i++) {
                const int idx = tid + i * 128;
                const int r = idx >> 3, c = idx & 7;
                cp_async16(Ks + r * FKS + c * 8, kn + (size_t)r * HDIM + c * 8);
            }
            cp_commit();
        }

        // ---- no-max softmax: p = bit ? exp(0.125*s) : 0 ----
        #pragma unroll
        for (int h = 0; h < 2; h++) {
            const unsigned long long m64 = mbits[h];
            float ls = 0.0f;
            #pragma unroll
            for (int nb = 0; nb < 8; nb++) {
                const int pos = nb * 8 + 2 * tid4;
                const float p0 = ((m64 >> pos) & 1ULL)
                               ? __expf(0.125f * S[nb][2 * h]) : 0.0f;
                const float p1 = ((m64 >> (pos + 1)) & 1ULL)
                               ? __expf(0.125f * S[nb][2 * h + 1]) : 0.0f;
                ls += p0 + p1;
                S[nb][2 * h]     = p0;
                S[nb][2 * h + 1] = p1;
            }
            lrow[h] += ls;
        }

        // wait for V(t); pending afterwards: only K(t+1) (if any)
        if (t0 + 64 < SEQ) cp_wait<1>(); else cp_wait<0>();
        __syncthreads();

        // ---- O += P @ V : P C-frag packs directly into A-frag (fp16) ----
        #pragma unroll
        for (int kt = 0; kt < 4; kt++) {
            unsigned a[4];
            a[0] = packh2(S[2 * kt][0],     S[2 * kt][1]);
            a[1] = packh2(S[2 * kt][2],     S[2 * kt][3]);
            a[2] = packh2(S[2 * kt + 1][0], S[2 * kt + 1][1]);
            a[3] = packh2(S[2 * kt + 1][2], S[2 * kt + 1][3]);
            #pragma unroll
            for (int nb = 0; nb < 8; nb++) {
                unsigned bf[2];
                const int vb = (nb * 8 + gid) * FVS + kt * 16 + 2 * tid4;
                bf[0] = *(const unsigned*)(Vs + vb);
                bf[1] = *(const unsigned*)(Vs + vb + 8);
                mma_f16(O[nb], a, bf);
            }
        }
        __syncthreads();       // all warps done reading V tile

        // prefetch next V tile (overlaps next QK)
        if (t0 + 64 < SEQ) {
            #pragma unroll
            for (int i = 0; i < 4; i++) {
                const int idx = tid + i * 128;
                const int r = idx >> 3, c = idx & 7;
                cp_async16(Vs + r * FVS + c * 8,
                           Vp + (size_t)r * SEQ + t0 + 64 + c * 8);
            }
            cp_commit();
        }
    }

    // ---- epilogue: reduce row sums once, normalize, store ----
    #pragma unroll
    for (int h = 0; h < 2; h++) {
        float l = lrow[h];
        l += __shfl_xor_sync(0xffffffffu, l, 1);
        l += __shfl_xor_sync(0xffffffffu, l, 2);
        const float linv = 1.0f / l;
        const int rg = f0 + w * 16 + gid + 8 * h;
        float* op = out + ((size_t)b * SEQ + rg) * HIDDEN + nh * HDIM;
        #pragma unroll
        for (int nb = 0; nb < 8; nb++) {
            float2 v;
            v.x = O[nb][2 * h] * linv;
            v.y = O[nb][2 * h + 1] * linv;
            *(float2*)(op + nb * 8 + 2 * tid4) = v;
        }
    }
}

// ---------------------------------------------------------------------------
// kernel_launch
// ---------------------------------------------------------------------------
extern "C" void kernel_launch(void* const* d_in, const int* in_sizes, int n_in,
                              void* d_out, int out_size)
{
    (void)in_sizes; (void)n_in; (void)out_size;

    const float* from_t = (const float*)d_in[0];
    const float* to_t   = (const float*)d_in[1];
    const int*   msk    = (const int*)d_in[2];
    const float* Wq     = (const float*)d_in[3];
    const float* bq     = (const float*)d_in[4];
    const float* Wk     = (const float*)d_in[5];
    const float* bk     = (const float*)d_in[6];
    const float* Wv     = (const float*)d_in[7];
    const float* bv     = (const float*)d_in[8];
    float* out = (float*)d_out;

    __half *qp, *kp, *vp; unsigned* mb;
    cudaGetSymbolAddress((void**)&qp, g_Qh);
    cudaGetSymbolAddress((void**)&kp, g_Kh);
    cudaGetSymbolAddress((void**)&vp, g_Vth);
    cudaGetSymbolAddress((void**)&mb, g_Mbits);

    cudaFuncSetAttribute(gemm_mma_kernel,
                         cudaFuncAttributeMaxDynamicSharedMemorySize, GEMM_SMEM);
    cudaFuncSetAttribute(flash_mma_kernel,
                         cudaFuncAttributeMaxDynamicSharedMemorySize, ATT_SMEM);

    // pack mask to bits (independent of GEMM outputs)
    mask_bits_kernel<<<(MROWS * 32 + 255) / 256, 256>>>(msk, mb);

    dim3 gg(HIDDEN / 128, MROWS / 128, 3);   // (8, 32, 3)
    gemm_mma_kernel<<<gg, 256, GEMM_SMEM>>>(from_t, to_t, Wq, bq, Wk, bk,
                                            Wv, bv, qp, kp, vp);

    dim3 gf(SEQ / 64, BATCH * NHEADS);       // (32, 32) = 1024 CTAs
    flash_mma_kernel<<<gf, 128, ATT_SMEM>>>(qp, kp, vp, mb, out);
}

// round 13
// speedup vs baseline: 1.6525x; 1.0909x over previous
#include <cuda_runtime.h>
#include <cuda_fp16.h>
#include <math.h>

// ---------------------------------------------------------------------------
// Attention_69226282877525: BERT-style MHA on sm_103a.
//   B=2, F=T=2048, HIDDEN=1024, N_HEADS=16, HEAD_DIM=64
// R13 = R12 flash (fp16 m16n8k16, unchanged) + GEMM mainloop moved to fp16
// m16n8k16 (half tiles, B stored [n][k] in SMEM, ktile 32, half the mma and
// barrier count of the tf32 version).
// ---------------------------------------------------------------------------

#define BATCH   2
#define SEQ     2048
#define HIDDEN  1024
#define NHEADS  16
#define HDIM    64
#define MROWS   (BATCH * SEQ)      // 4096

// Scratch (half): Q/K in [B][N][S][H]; V TRANSPOSED in [B][N][H][S].
__device__ __half g_Qh[(size_t)BATCH * NHEADS * SEQ * HDIM];
__device__ __half g_Kh[(size_t)BATCH * NHEADS * SEQ * HDIM];
__device__ __half g_Vth[(size_t)BATCH * NHEADS * SEQ * HDIM];
// Packed attention mask bits: [B][F][T/32]
__device__ unsigned g_Mbits[(size_t)BATCH * SEQ * (SEQ / 32)];

// --------------------------- helpers ---------------------------------------
__device__ __forceinline__ void mma_f16(float c[4], const unsigned a[4],
                                        const unsigned b[2]) {
    asm volatile(
        "mma.sync.aligned.m16n8k16.row.col.f32.f16.f16.f32 "
        "{%0,%1,%2,%3}, {%4,%5,%6,%7}, {%8,%9}, {%0,%1,%2,%3};\n"
        : "+f"(c[0]), "+f"(c[1]), "+f"(c[2]), "+f"(c[3])
        : "r"(a[0]), "r"(a[1]), "r"(a[2]), "r"(a[3]), "r"(b[0]), "r"(b[1]));
}
__device__ __forceinline__ unsigned packh2(float x, float y) {
    __half2 h = __floats2half2_rn(x, y);
    return *(unsigned*)&h;
}
__device__ __forceinline__ void cp_async16(void* dst_smem, const void* src) {
    unsigned d = (unsigned)__cvta_generic_to_shared(dst_smem);
    asm volatile("cp.async.cg.shared.global [%0], [%1], 16;" :: "r"(d), "l"(src));
}
__device__ __forceinline__ void cp_commit() {
    asm volatile("cp.async.commit_group;");
}
template<int N> __device__ __forceinline__ void cp_wait() {
    asm volatile("cp.async.wait_group %0;" :: "n"(N));
}

// ---------------------------------------------------------------------------
// Pack mask [B,F,T] int32 -> bitmask [B,F,T/32]. One warp per (b,f) row.
// ---------------------------------------------------------------------------
__global__ __launch_bounds__(256) void mask_bits_kernel(
    const int* __restrict__ mask, unsigned* __restrict__ bits)
{
    const int gw   = (blockIdx.x * 256 + threadIdx.x) >> 5;
    const int lane = threadIdx.x & 31;
    if (gw >= BATCH * SEQ) return;
    const int* mp = mask + (size_t)gw * SEQ;
    unsigned* bp  = bits + (size_t)gw * (SEQ / 32);
    #pragma unroll 4
    for (int c = 0; c < SEQ / 32; c++) {
        const int v = mp[c * 32 + lane];
        const unsigned w = __ballot_sync(0xffffffffu, v != 0);
        if (lane == 0) bp[c] = w;
    }
}

// ---------------------------------------------------------------------------
// Merged QKV projection GEMM (fp16 m16n8k16 mainloop, half outputs).
// blockIdx.z in {Q,K,V}. Tile 128x128, ktile 32 (2 substeps of k16),
// 8 warps (4m x 2n), warp tile 32x64. A [m][k] half; B [n][k] half (staged
// transposed). Q/K out: [B][N][S][H]; V out: [B][N][H][S] via smem transpose.
// ---------------------------------------------------------------------------
#define ASTR 40     // halves per A row (32 + 8 pad)
#define BSTR 38     // halves per B row (32 + 6 pad)
#define GA_HSZ (128 * ASTR)
#define GB_HSZ (128 * BSTR)
#define VT_STR 136  // transpose buffer stride (halves): 128x136 = 34816 B
#define GEMM_SMEM ((2 * GA_HSZ + 2 * GB_HSZ) * 2)   // 39936 B (>= 34816)

__global__ __launch_bounds__(256, 2) void gemm_mma_kernel(
    const float* __restrict__ Xq, const float* __restrict__ Xkv,
    const float* __restrict__ Wq, const float* __restrict__ bq,
    const float* __restrict__ Wk, const float* __restrict__ bk,
    const float* __restrict__ Wv, const float* __restrict__ bv,
    __half* __restrict__ oq, __half* __restrict__ ok, __half* __restrict__ ov)
{
    extern __shared__ __half smh[];
    __half* Ah = smh;                      // [2][128][ASTR]
    __half* Bh = smh + 2 * GA_HSZ;         // [2][128 n][BSTR]

    const float* X; const float* W; const float* bias; __half* out;
    if (blockIdx.z == 0)      { X = Xq;  W = Wq; bias = bq; out = oq; }
    else if (blockIdx.z == 1) { X = Xkv; W = Wk; bias = bk; out = ok; }
    else                      { X = Xkv; W = Wv; bias = bv; out = ov; }
    const bool vtrans = (blockIdx.z == 2);

    const int tid  = threadIdx.x;
    const int w    = tid >> 5;
    const int lane = tid & 31;
    const int gid  = lane >> 2;
    const int tid4 = lane & 3;
    const int wm   = w & 3;
    const int wn   = w >> 2;
    const int row0 = blockIdx.y * 128;
    const int col0 = blockIdx.x * 128;

    float4 ar[4], br[4];

    // prologue: load k-tile 0
    #pragma unroll
    for (int i = 0; i < 4; i++) {
        const int idx = tid + i * 256;
        { const int r = idx >> 3, c = idx & 7;     // A: 128 x 8 float4
          ar[i] = *(const float4*)(X + (size_t)(row0 + r) * HIDDEN + c * 4); }
        { const int r = idx >> 5, c = idx & 31;    // B: 32 x 32 float4
          br[i] = *(const float4*)(W + (size_t)r * HIDDEN + col0 + c * 4); }
    }
    #pragma unroll
    for (int i = 0; i < 4; i++) {
        const int idx = tid + i * 256;
        { const int r = idx >> 3, c = idx & 7;
          __half* p = Ah + r * ASTR + c * 4;
          *(unsigned*)p       = packh2(ar[i].x, ar[i].y);
          *(unsigned*)(p + 2) = packh2(ar[i].z, ar[i].w); }
        { const int r = idx >> 5, c = idx & 31;    // -> B[n][k]
          Bh[(c * 4 + 0) * BSTR + r] = __float2half_rn(br[i].x);
          Bh[(c * 4 + 1) * BSTR + r] = __float2half_rn(br[i].y);
          Bh[(c * 4 + 2) * BSTR + r] = __float2half_rn(br[i].z);
          Bh[(c * 4 + 3) * BSTR + r] = __float2half_rn(br[i].w); }
    }
    __syncthreads();

    float C[2][8][4] = {};

    for (int kt = 0; kt < 32; kt++) {
        const int buf = kt & 1;
        if (kt < 31) {
            const int k0 = (kt + 1) * 32;
            #pragma unroll
            for (int i = 0; i < 4; i++) {
                const int idx = tid + i * 256;
                { const int r = idx >> 3, c = idx & 7;
                  ar[i] = *(const float4*)(X + (size_t)(row0 + r) * HIDDEN + k0 + c * 4); }
                { const int r = idx >> 5, c = idx & 31;
                  br[i] = *(const float4*)(W + (size_t)(k0 + r) * HIDDEN + col0 + c * 4); }
            }
        }
        const __half* Ab = Ah + buf * GA_HSZ;
        const __half* Bb = Bh + buf * GB_HSZ;
        #pragma unroll
        for (int ks = 0; ks < 2; ks++) {
            unsigned a[2][4];
            #pragma unroll
            for (int mb = 0; mb < 2; mb++) {
                const int base = (wm * 32 + mb * 16 + gid) * ASTR + ks * 16 + 2 * tid4;
                a[mb][0] = *(const unsigned*)(Ab + base);
                a[mb][1] = *(const unsigned*)(Ab + base + 8 * ASTR);
                a[mb][2] = *(const unsigned*)(Ab + base + 8);
                a[mb][3] = *(const unsigned*)(Ab + base + 8 * ASTR + 8);
            }
            #pragma unroll
            for (int nb = 0; nb < 8; nb++) {
                const int n = wn * 64 + nb * 8 + gid;
                unsigned bf[2];
                bf[0] = *(const unsigned*)(Bb + n * BSTR + ks * 16 + 2 * tid4);
                bf[1] = *(const unsigned*)(Bb + n * BSTR + ks * 16 + 2 * tid4 + 8);
                mma_f16(C[0][nb], a[0], bf);
                mma_f16(C[1][nb], a[1], bf);
            }
        }
        if (kt < 31) {
            __half* An = Ah + ((kt + 1) & 1) * GA_HSZ;
            __half* Bn = Bh + ((kt + 1) & 1) * GB_HSZ;
            #pragma unroll
            for (int i = 0; i < 4; i++) {
                const int idx = tid + i * 256;
                { const int r = idx >> 3, c = idx & 7;
                  __half* p = An + r * ASTR + c * 4;
                  *(unsigned*)p       = packh2(ar[i].x, ar[i].y);
                  *(unsigned*)(p + 2) = packh2(ar[i].z, ar[i].w); }
                { const int r = idx >> 5, c = idx & 31;
                  Bn[(c * 4 + 0) * BSTR + r] = __float2half_rn(br[i].x);
                  Bn[(c * 4 + 1) * BSTR + r] = __float2half_rn(br[i].y);
                  Bn[(c * 4 + 2) * BSTR + r] = __float2half_rn(br[i].z);
                  Bn[(c * 4 + 3) * BSTR + r] = __float2half_rn(br[i].w); }
            }
        }
        __syncthreads();
    }

    const int colbase = col0 + wn * 64;
    const int nhead   = colbase >> 6;

    if (!vtrans) {
        // Q/K: half2 store to [B][N][S][H]
        #pragma unroll
        for (int mb = 0; mb < 2; mb++) {
            #pragma unroll
            for (int h = 0; h < 2; h++) {
                const int row = row0 + wm * 32 + mb * 16 + gid + 8 * h;
                const int b   = row >> 11;
                const int s   = row & 2047;
                __half* op = out + (((size_t)b * NHEADS + nhead) * SEQ + s) * HDIM;
                #pragma unroll
                for (int nb = 0; nb < 8; nb++) {
                    const int hh = nb * 8 + 2 * tid4;
                    const unsigned v = packh2(C[mb][nb][2 * h]     + bias[colbase + hh],
                                              C[mb][nb][2 * h + 1] + bias[colbase + hh + 1]);
                    *(unsigned*)(op + hh) = v;
                }
            }
        }
    } else {
        // V: transpose through smem, store [B][N][H][S] half, coalesced.
        __half* T = smh;                   // [128 h][VT_STR]
        #pragma unroll
        for (int mb = 0; mb < 2; mb++) {
            #pragma unroll
            for (int h = 0; h < 2; h++) {
                const int srow = wm * 32 + mb * 16 + gid + 8 * h;   // 0..127
                #pragma unroll
                for (int nb = 0; nb < 8; nb++) {
                    const int hh = wn * 64 + nb * 8 + 2 * tid4;     // tile col
                    T[(size_t)hh * VT_STR + srow] =
                        __float2half_rn(C[mb][nb][2 * h] + bias[col0 + hh]);
                    T[(size_t)(hh + 1) * VT_STR + srow] =
                        __float2half_rn(C[mb][nb][2 * h + 1] + bias[col0 + hh + 1]);
                }
            }
        }
        __syncthreads();
        // cooperative coalesced store: 2 threads per h-row, 64 halves each
        const int r   = tid >> 1;              // 0..127 (tile col = h)
        const int seg = (tid & 1) * 64;        // s segment
        const int hg  = col0 + r;
        const int n   = hg >> 6;
        const int hl  = hg & 63;
        const int b   = row0 >> 11;
        const int sb  = (row0 & 2047) + seg;
        __half* op = ov + (((size_t)b * NHEADS + n) * HDIM + hl) * SEQ + sb;
        const uint4* Tr = (const uint4*)(T + (size_t)r * VT_STR + seg);
        #pragma unroll
        for (int j = 0; j < 8; j++)
            ((uint4*)op)[j] = Tr[j];
    }
}

// ---------------------------------------------------------------------------
// Flash attention (fp16 m16n8k16): CTA 128 thr = 4 warps x 16 f-rows,
// f-tile 64, T-tile 64. Q fragments in registers (loaded once). K [t][h] and
// V^T [h][t] half tiles in SMEM (18.4KB), single-buffered with split waits.
// QK C-frag feeds PV A-frag directly (no shuffles). No-max softmax; bitmask.
// (Byte-identical to R12.)
// ---------------------------------------------------------------------------
#define FKS 72      // K tile row stride (halves)
#define FVS 72      // VT tile row stride (halves)
#define ATT_SMEM ((64 * FKS + 64 * FVS) * 2)   // 18432 bytes

__global__ __launch_bounds__(128, 4) void flash_mma_kernel(
    const __half* __restrict__ Q, const __half* __restrict__ K,
    const __half* __restrict__ Vt, const unsigned* __restrict__ mbitsg,
    float* __restrict__ out)
{
    extern __shared__ __half smhf[];
    __half* Ks = smhf;                     // [64 t][FKS]
    __half* Vs = smhf + 64 * FKS;          // [64 h][FVS]

    const int tid  = threadIdx.x;          // 128
    const int w    = tid >> 5;             // 0..3 -> f-rows w*16..w*16+15
    const int lane = tid & 31;
    const int gid  = lane >> 2;
    const int tid4 = lane & 3;

    const int bn = blockIdx.y;             // b*16 + head
    const int b  = bn >> 4;
    const int nh = bn & 15;
    const int f0 = blockIdx.x * 64;

    const __half* Kp = K + (size_t)bn * SEQ * HDIM;    // [t][h]
    const __half* Vp = Vt + (size_t)bn * HDIM * SEQ;   // [h][t]
    const unsigned* Mb = mbitsg + (size_t)b * SEQ * (SEQ / 32);

    // prologue: K0 (group 0), V0 (group 1). Tile = 64 rows x 128B.
    #pragma unroll
    for (int i = 0; i < 4; i++) {
        const int idx = tid + i * 128;
        const int r = idx >> 3, c = idx & 7;
        cp_async16(Ks + r * FKS + c * 8, Kp + (size_t)r * HDIM + c * 8);
    }
    cp_commit();
    #pragma unroll
    for (int i = 0; i < 4; i++) {
        const int idx = tid + i * 128;
        const int r = idx >> 3, c = idx & 7;
        cp_async16(Vs + r * FVS + c * 8, Vp + (size_t)r * SEQ + c * 8);
    }
    cp_commit();

    // Q fragments in registers: a-frags for m16n8k16 (half2 words)
    unsigned qf[4][4];
    {
        const __half* Qw = Q + ((size_t)bn * SEQ + f0 + w * 16) * HDIM;
        #pragma unroll
        for (int ks = 0; ks < 4; ks++) {
            const int c = ks * 16 + 2 * tid4;
            qf[ks][0] = *(const unsigned*)(Qw + (size_t)gid * HDIM + c);
            qf[ks][1] = *(const unsigned*)(Qw + (size_t)(gid + 8) * HDIM + c);
            qf[ks][2] = *(const unsigned*)(Qw + (size_t)gid * HDIM + c + 8);
            qf[ks][3] = *(const unsigned*)(Qw + (size_t)(gid + 8) * HDIM + c + 8);
        }
    }

    float O[8][4] = {};
    float lrow[2] = {};

    for (int t0 = 0; t0 < SEQ; t0 += 64) {
        cp_wait<1>();          // K(t) ready (V(t) may still be in flight)
        __syncthreads();

        // mask bits for this tile (hidden behind QK mma)
        unsigned long long mbits[2];
        #pragma unroll
        for (int h = 0; h < 2; h++) {
            const int rg = f0 + w * 16 + gid + 8 * h;
            const uint2 mm = *(const uint2*)(Mb + (size_t)rg * (SEQ / 32) + (t0 >> 5));
            mbits[h] = (unsigned long long)mm.x |
                       ((unsigned long long)mm.y << 32);
        }

        // ---- S = Q @ K^T (fp16, warp tile 16x64) ----
        float S[8][4] = {};
        #pragma unroll
        for (int ks = 0; ks < 4; ks++) {
            #pragma unroll
            for (int nb = 0; nb < 8; nb++) {
                unsigned bf[2];
                const int bb = (nb * 8 + gid) * FKS + ks * 16 + 2 * tid4;
                bf[0] = *(const unsigned*)(Ks + bb);
                bf[1] = *(const unsigned*)(Ks + bb + 8);
                mma_f16(S[nb], qf[ks], bf);
            }
        }
        __syncthreads();       // all warps done reading K tile

        // prefetch next K tile (overlaps softmax + PV)
        if (t0 + 64 < SEQ) {
            const __half* kn = Kp + (size_t)(t0 + 64) * HDIM;
            #pragma unroll
            for (int i = 0; i < 4; i++) {
                const int idx = tid + i * 128;
                const int r = idx >> 3, c = idx & 7;
                cp_async16(Ks + r * FKS + c * 8, kn + (size_t)r * HDIM + c * 8);
            }
            cp_commit();
        }

        // ---- no-max softmax: p = bit ? exp(0.125*s) : 0 ----
        #pragma unroll
        for (int h = 0; h < 2; h++) {
            const unsigned long long m64 = mbits[h];
            float ls = 0.0f;
            #pragma unroll
            for (int nb = 0; nb < 8; nb++) {
                const int pos = nb * 8 + 2 * tid4;
                const float p0 = ((m64 >> pos) & 1ULL)
                               ? __expf(0.125f * S[nb][2 * h]) : 0.0f;
                const float p1 = ((m64 >> (pos + 1)) & 1ULL)
                               ? __expf(0.125f * S[nb][2 * h + 1]) : 0.0f;
                ls += p0 + p1;
                S[nb][2 * h]     = p0;
                S[nb][2 * h + 1] = p1;
            }
            lrow[h] += ls;
        }

        // wait for V(t); pending afterwards: only K(t+1) (if any)
        if (t0 + 64 < SEQ) cp_wait<1>(); else cp_wait<0>();
        __syncthreads();

        // ---- O += P @ V : P C-frag packs directly into A-frag (fp16) ----
        #pragma unroll
        for (int kt = 0; kt < 4; kt++) {
            unsigned a[4];
            a[0] = packh2(S[2 * kt][0],     S[2 * kt][1]);
            a[1] = packh2(S[2 * kt][2],     S[2 * kt][3]);
            a[2] = packh2(S[2 * kt + 1][0], S[2 * kt + 1][1]);
            a[3] = packh2(S[2 * kt + 1][2], S[2 * kt + 1][3]);
            #pragma unroll
            for (int nb = 0; nb < 8; nb++) {
                unsigned bf[2];
                const int vb = (nb * 8 + gid) * FVS + kt * 16 + 2 * tid4;
                bf[0] = *(const unsigned*)(Vs + vb);
                bf[1] = *(const unsigned*)(Vs + vb + 8);
                mma_f16(O[nb], a, bf);
            }
        }
        __syncthreads();       // all warps done reading V tile

        // prefetch next V tile (overlaps next QK)
        if (t0 + 64 < SEQ) {
            #pragma unroll
            for (int i = 0; i < 4; i++) {
                const int idx = tid + i * 128;
                const int r = idx >> 3, c = idx & 7;
                cp_async16(Vs + r * FVS + c * 8,
                           Vp + (size_t)r * SEQ + t0 + 64 + c * 8);
            }
            cp_commit();
        }
    }

    // ---- epilogue: reduce row sums once, normalize, store ----
    #pragma unroll
    for (int h = 0; h < 2; h++) {
        float l = lrow[h];
        l += __shfl_xor_sync(0xffffffffu, l, 1);
        l += __shfl_xor_sync(0xffffffffu, l, 2);
        const float linv = 1.0f / l;
        const int rg = f0 + w * 16 + gid + 8 * h;
        float* op = out + ((size_t)b * SEQ + rg) * HIDDEN + nh * HDIM;
        #pragma unroll
        for (int nb = 0; nb < 8; nb++) {
            float2 v;
            v.x = O[nb][2 * h] * linv;
            v.y = O[nb][2 * h + 1] * linv;
            *(float2*)(op + nb * 8 + 2 * tid4) = v;
        }
    }
}

// ---------------------------------------------------------------------------
// kernel_launch
// ---------------------------------------------------------------------------
extern "C" void kernel_launch(void* const* d_in, const int* in_sizes, int n_in,
                              void* d_out, int out_size)
{
    (void)in_sizes; (void)n_in; (void)out_size;

    const float* from_t = (const float*)d_in[0];
    const float* to_t   = (const float*)d_in[1];
    const int*   msk    = (const int*)d_in[2];
    const float* Wq     = (const float*)d_in[3];
    const float* bq     = (const float*)d_in[4];
    const float* Wk     = (const float*)d_in[5];
    const float* bk     = (const float*)d_in[6];
    const float* Wv     = (const float*)d_in[7];
    const float* bv     = (const float*)d_in[8];
    float* out = (float*)d_out;

    __half *qp, *kp, *vp; unsigned* mb;
    cudaGetSymbolAddress((void**)&qp, g_Qh);
    cudaGetSymbolAddress((void**)&kp, g_Kh);
    cudaGetSymbolAddress((void**)&vp, g_Vth);
    cudaGetSymbolAddress((void**)&mb, g_Mbits);

    cudaFuncSetAttribute(gemm_mma_kernel,
                         cudaFuncAttributeMaxDynamicSharedMemorySize, GEMM_SMEM);
    cudaFuncSetAttribute(flash_mma_kernel,
                         cudaFuncAttributeMaxDynamicSharedMemorySize, ATT_SMEM);

    // pack mask to bits (independent of GEMM outputs)
    mask_bits_kernel<<<(MROWS * 32 + 255) / 256, 256>>>(msk, mb);

    dim3 gg(HIDDEN / 128, MROWS / 128, 3);   // (8, 32, 3)
    gemm_mma_kernel<<<gg, 256, GEMM_SMEM>>>(from_t, to_t, Wq, bq, Wk, bk,
                                            Wv, bv, qp, kp, vp);

    dim3 gf(SEQ / 64, BATCH * NHEADS);       // (32, 32) = 1024 CTAs
    flash_mma_kernel<<<gf, 128, ATT_SMEM>>>(qp, kp, vp, mb, out);
}